// round 2
// baseline (speedup 1.0000x reference)
#include <cuda_runtime.h>
#include <cstdint>

#define NA     17064
#define KTOP   1000
#define NBINS  16384
#define CCAP   4096
#define NT     1024

// ---- shared memory arena (byte offsets) ----
// phase 1-3 aliases:
#define OFF_SCORES 0         // float[17064]  = 68256
#define OFF_HIST   68256     // u32[16384]    = 65536 (ends 133792)
#define OFF_CAND   68256     // u64[4096]     = 32768 (reuses hist after threshold found)
#define OFF_CHUNK  133792    // u32[1024]
// phase 4+ persistent:
#define OFF_MAT    0         // u32[1000*32]  = 128000 (reuses scores region)
#define OFF_SX1    128000
#define OFF_SY1    132000
#define OFF_SX2    136000
#define OFF_SY2    140000
#define OFF_AREA   144000
#define OFF_BOX    148000    // float4[1000] = 16000
#define OFF_SCORE  164000
#define OFF_LABEL  168000
#define OFF_VALID  172000
#define OFF_KEEP   176000
#define OFF_SCAL   180000
#define SMEM_TOTAL 180992

struct Scal {
    unsigned cnt;
    unsigned thr;
    float mx, mn;
    float redmax[32];
    float redmin[32];
};

// Fast approximate sigmoid — used ONLY to select a candidate superset.
__device__ __forceinline__ float sigf(float x) {
    return __fdiv_rn(1.0f, __fadd_rn(1.0f, __expf(x == x ? -x : -x) * 0.0f + expf(-x)));
}

// Exact sigmoid: float exp replicated via double exp (correctly-rounded float
// result ⇒ matches any faithfully-rounded libm expf), then float add + div
// exactly as XLA's expanded logistic does.
__device__ __forceinline__ float sigx(float x) {
    float t = (float)exp(-(double)x);
    return __fdiv_rn(1.0f, __fadd_rn(1.0f, t));
}

extern __shared__ unsigned char smem_raw[];

__global__ void __launch_bounds__(NT, 1)
fcos_kernel(const float* __restrict__ cls,
            const float* __restrict__ ctr,
            const float* __restrict__ reg,
            const float* __restrict__ coords,
            const float* __restrict__ pstr,
            float* __restrict__ out)
{
    const int b    = blockIdx.x;
    const int tid  = threadIdx.x;
    const int lane = tid & 31;
    const int wid  = tid >> 5;

    float*              scores = (float*)(smem_raw + OFF_SCORES);
    unsigned*           hist   = (unsigned*)(smem_raw + OFF_HIST);
    unsigned long long* cand   = (unsigned long long*)(smem_raw + OFF_CAND);
    unsigned*           chunk  = (unsigned*)(smem_raw + OFF_CHUNK);
    unsigned*           mat    = (unsigned*)(smem_raw + OFF_MAT);
    float*  sx1  = (float*)(smem_raw + OFF_SX1);
    float*  sy1  = (float*)(smem_raw + OFF_SY1);
    float*  sx2  = (float*)(smem_raw + OFF_SX2);
    float*  sy2  = (float*)(smem_raw + OFF_SY2);
    float*  sar  = (float*)(smem_raw + OFF_AREA);
    float4* sbox = (float4*)(smem_raw + OFF_BOX);
    float*  ssc  = (float*)(smem_raw + OFF_SCORE);
    unsigned* slab  = (unsigned*)(smem_raw + OFF_LABEL);
    unsigned* sval  = (unsigned*)(smem_raw + OFF_VALID);
    unsigned* skeep = (unsigned*)(smem_raw + OFF_KEEP);
    Scal* sc = (Scal*)(smem_raw + OFF_SCAL);

    const float4* clsB = (const float4*)cls + (size_t)b * NA;
    const float*  ctrB = ctr + (size_t)b * NA;
    const float4* regB = (const float4*)reg + (size_t)b * NA;

    // ---------------- Phase 1: approx scores + histogram ----------------
    for (int i = tid; i < NBINS; i += NT) hist[i] = 0;
    if (tid == 0) sc->cnt = 0;
    __syncthreads();

    for (int i = tid; i < NA; i += NT) {
        float4 c4 = clsB[i];
        float s0 = sigf(c4.x), s1 = sigf(c4.y), s2 = sigf(c4.z), s3 = sigf(c4.w);
        float m = fmaxf(fmaxf(s0, s1), fmaxf(s2, s3));
        float sctr = sigf(ctrB[i]);
        float score = __fsqrt_rn(__fmul_rn(m, sctr));
        scores[i] = score;
        atomicAdd(&hist[__float_as_uint(score) >> 16], 1u);
    }
    __syncthreads();

    // ---------------- Phase 1b: find threshold bin (≥ KTOP above it) ----------------
    {
        unsigned s = 0;
        int base = tid * 16;
#pragma unroll
        for (int q = 0; q < 16; ++q) s += hist[base + q];
        chunk[tid] = s;
    }
    __syncthreads();
    if (tid == 0) {
        unsigned acc = 0; int T = 0;
        for (int c = 1023; c >= 0; --c) {
            unsigned a2 = acc + chunk[c];
            if (a2 >= KTOP) {
                for (int bin = c * 16 + 15; bin >= c * 16; --bin) {
                    acc += hist[bin];
                    if (acc >= KTOP) { T = bin; break; }
                }
                break;
            }
            acc = a2;
        }
        // lower by one bin: superset margin covers approx-vs-exact ULP error
        sc->thr = (unsigned)(T > 0 ? T - 1 : 0);
    }
    __syncthreads();
    const unsigned T = sc->thr;

    // ---------------- Phase 2: compact candidate superset ----------------
    for (int i = tid; i < NA; i += NT) {
        unsigned bits = __float_as_uint(scores[i]);
        if ((bits >> 16) >= T) {
            unsigned p = atomicAdd(&sc->cnt, 1u);
            if (p < CCAP)
                cand[p] = ((unsigned long long)bits << 32) |
                          (unsigned long long)(0xFFFFFFFFu - (unsigned)i);
        }
    }
    __syncthreads();
    unsigned C = sc->cnt; if (C > CCAP) C = CCAP;

    // ---------------- Phase 2b: exact rescore of candidates (double exp) ----------
    for (int p = tid; p < (int)C; p += NT) {
        unsigned idx = 0xFFFFFFFFu - (unsigned)(cand[p] & 0xFFFFFFFFull);
        float4 c4 = clsB[idx];
        float s0 = sigx(c4.x), s1 = sigx(c4.y), s2 = sigx(c4.z), s3 = sigx(c4.w);
        float m = fmaxf(fmaxf(s0, s1), fmaxf(s2, s3));
        float sctr = sigx(ctrB[idx]);
        float score = __fsqrt_rn(__fmul_rn(m, sctr));
        cand[p] = ((unsigned long long)__float_as_uint(score) << 32) |
                  (unsigned long long)(0xFFFFFFFFu - idx);
    }
    const int S = ((int)C <= 2048) ? 2048 : CCAP;   // sort size
    for (int i = tid; i < S; i += NT) if (i >= (int)C) cand[i] = 0ULL;
    __syncthreads();

    // ---------------- Phase 3: bitonic sort S, descending ----------------
    for (int k2 = 2; k2 <= S; k2 <<= 1) {
        for (int j = k2 >> 1; j > 0; j >>= 1) {
            for (int t = tid; t < S; t += NT) {
                int ixj = t ^ j;
                if (ixj > t) {
                    unsigned long long a  = cand[t];
                    unsigned long long b2 = cand[ixj];
                    bool up = ((t & k2) == 0);
                    if (up ? (a < b2) : (a > b2)) { cand[t] = b2; cand[ixj] = a; }
                }
            }
            __syncthreads();
        }
    }

    // ---------------- Phase 4: gather top-1000, boxes, labels (exact sigmoids) ----
    float x1 = 0.f, y1 = 0.f, x2 = 0.f, y2 = 0.f, score = 0.f;
    int label = 0; bool validf = false;
    if (tid < KTOP) {
        unsigned long long key = cand[tid];
        unsigned sb = (unsigned)(key >> 32);
        score = __uint_as_float(sb);
        int idx = (int)(0xFFFFFFFFu - (unsigned)(key & 0xFFFFFFFFull));
        validf = (score >= 0.05f);

        float4 c4 = clsB[idx];
        float s0 = sigx(c4.x), s1 = sigx(c4.y), s2 = sigx(c4.z), s3 = sigx(c4.w);
        float m = s0; label = 1;
        if (s1 > m) { m = s1; label = 2; }
        if (s2 > m) { m = s2; label = 3; }
        if (s3 > m) { m = s3; label = 4; }

        float4 r4 = regB[idx];
        float2 xy = ((const float2*)coords)[idx];
        float st = pstr[idx];
        x1 = __fsub_rn(xy.x, __fmul_rn(r4.x, st));
        y1 = __fsub_rn(xy.y, __fmul_rn(r4.y, st));
        x2 = __fadd_rn(xy.x, __fmul_rn(r4.z, st));
        y2 = __fadd_rn(xy.y, __fmul_rn(r4.w, st));
        x1 = fminf(fmaxf(x1, 0.0f), 1023.0f);
        y1 = fminf(fmaxf(y1, 0.0f), 799.0f);
        x2 = fminf(fmaxf(x2, 0.0f), 1023.0f);
        y2 = fminf(fmaxf(y2, 0.0f), 799.0f);

        sbox[tid] = make_float4(x1, y1, x2, y2);
        ssc[tid]  = score;
        slab[tid] = (unsigned)label;
        sval[tid] = validf ? 1u : 0u;
    }

    // ---------------- Phase 5: mx/mn over valid boxes, shifted boxes + areas ------
    float vmax = -1000000000.0f, vmin = 1000000000.0f;
    if (tid < KTOP && validf) {
        vmax = fmaxf(fmaxf(x1, y1), fmaxf(x2, y2));
        vmin = fminf(fminf(x1, y1), fminf(x2, y2));
    }
#pragma unroll
    for (int o = 16; o; o >>= 1) {
        vmax = fmaxf(vmax, __shfl_xor_sync(0xffffffffu, vmax, o));
        vmin = fminf(vmin, __shfl_xor_sync(0xffffffffu, vmin, o));
    }
    if (lane == 0) { sc->redmax[wid] = vmax; sc->redmin[wid] = vmin; }
    __syncthreads();
    if (tid == 0) {
        float mx = sc->redmax[0], mn = sc->redmin[0];
        for (int w = 1; w < 32; ++w) {
            mx = fmaxf(mx, sc->redmax[w]);
            mn = fminf(mn, sc->redmin[w]);
        }
        sc->mx = mx; sc->mn = mn;
    }
    __syncthreads();

    if (tid < KTOP) {
        float off = __fmul_rn((float)label, __fadd_rn(__fsub_rn(sc->mx, sc->mn), 1.0f));
        float a  = __fadd_rn(x1, off), bb = __fadd_rn(y1, off);
        float cc = __fadd_rn(x2, off), dd = __fadd_rn(y2, off);
        sx1[tid] = a; sy1[tid] = bb; sx2[tid] = cc; sy2[tid] = dd;
        sar[tid] = __fmul_rn(__fsub_rn(cc, a), __fsub_rn(dd, bb));
    }
    __syncthreads();

    // ---------------- Phase 6: suppression bit-matrix (warp per row, ballot) ------
    for (int i = wid; i < KTOP; i += 32) {
        float ax1 = sx1[i], ay1 = sy1[i], ax2 = sx2[i], ay2 = sy2[i], aa = sar[i];
        unsigned myword = 0;
        for (int jc = 0; jc < 32; ++jc) {
            int jbase = jc * 32;
            unsigned wbits = 0;
            if (jbase + 31 > i) {               // uniform per warp
                int j = jbase + lane;
                bool sup = false;
                if (j > i && j < KTOP) {
                    float ix1 = fmaxf(ax1, sx1[j]);
                    float iy1 = fmaxf(ay1, sy1[j]);
                    float ix2 = fminf(ax2, sx2[j]);
                    float iy2 = fminf(ay2, sy2[j]);
                    float iw  = fmaxf(__fsub_rn(ix2, ix1), 0.0f);
                    float ih  = fmaxf(__fsub_rn(iy2, iy1), 0.0f);
                    float inter = __fmul_rn(iw, ih);
                    float uni = fmaxf(__fsub_rn(__fadd_rn(aa, sar[j]), inter), 1e-9f);
                    float iou = __fdiv_rn(inter, uni);
                    sup = iou > 0.5f;
                }
                wbits = __ballot_sync(0xffffffffu, sup);
            }
            if (lane == jc) myword = wbits;
        }
        mat[i * 32 + lane] = myword;
    }
    __syncthreads();

    // ---------------- Phase 7: serial greedy NMS on warp 0 ----------------
    if (wid == 0) {
        unsigned removed = 0;                    // lane l owns candidates [32l, 32l+32)
#pragma unroll
        for (int jj = 0; jj < 32; ++jj) {
            int j = lane * 32 + jj;
            unsigned v = (j < KTOP) ? sval[j] : 0u;
            removed |= (v ? 0u : 1u) << jj;
        }
        for (int i = 0; i < KTOP; ++i) {
            unsigned row  = mat[i * 32 + lane];
            unsigned rsrc = __shfl_sync(0xffffffffu, removed, i >> 5);
            bool kept = ((rsrc >> (i & 31)) & 1u) == 0u;
            if (kept) removed |= row;
            if (lane == 0) skeep[i] = kept ? 1u : 0u;
        }
    }
    __syncthreads();

    // ---------------- Phase 8: outputs (scores | labels | boxes, all f32) ---------
    if (tid < KTOP) {
        bool k = skeep[tid] != 0;
        float so = k ? ssc[tid] : 0.0f;
        float lo = k ? (float)slab[tid] : 0.0f;
        float4 bx = sbox[tid];
        if (!k) bx = make_float4(0.f, 0.f, 0.f, 0.f);
        out[(size_t)b * KTOP + tid] = so;
        out[(size_t)(16 * KTOP) + (size_t)b * KTOP + tid] = lo;
        size_t base = (size_t)(32 * KTOP) + ((size_t)b * KTOP + tid) * 4;
        out[base + 0] = bx.x;
        out[base + 1] = bx.y;
        out[base + 2] = bx.z;
        out[base + 3] = bx.w;
    }
}

extern "C" void kernel_launch(void* const* d_in, const int* in_sizes, int n_in,
                              void* d_out, int out_size) {
    (void)in_sizes; (void)n_in; (void)out_size;
    cudaFuncSetAttribute(fcos_kernel, cudaFuncAttributeMaxDynamicSharedMemorySize, SMEM_TOTAL);
    fcos_kernel<<<16, NT, SMEM_TOTAL>>>(
        (const float*)d_in[0],   // cls_logits [16,17064,4]
        (const float*)d_in[1],   // ctr_logits [16,17064,1]
        (const float*)d_in[2],   // reg_preds  [16,17064,4]
        (const float*)d_in[3],   // coords     [17064,2]
        (const float*)d_in[4],   // point_strides [17064]
        (float*)d_out);          // [16000 scores | 16000 labels | 64000 boxes]
}

// round 3
// speedup vs baseline: 1.7738x; 1.7738x over previous
#include <cuda_runtime.h>
#include <cstdint>

#define NA     17064
#define KTOP   1000
#define NBINS  16384
#define CCAP   4096
#define B      16

// ---------------- static device scratch (no runtime alloc) ----------------
__device__ float              gscore[B][NA];
__device__ unsigned           gcidx[B][CCAP];
__device__ unsigned           gcnt[B];
__device__ unsigned long long gkey[B][CCAP];
__device__ float              gssc[B][KTOP];
__device__ unsigned           gslab[B][KTOP];
__device__ unsigned           gsval[B][KTOP];
__device__ float4             gsbox[B][KTOP];
__device__ float              gsx1[B][KTOP], gsy1[B][KTOP], gsx2[B][KTOP],
                              gsy2[B][KTOP], gsar[B][KTOP];
__device__ unsigned           gmat[B][KTOP][32];

// Exact sigmoid: float exp replicated via double exp (correctly rounded to
// float => matches faithful libm expf), then float add + div as XLA expands.
__device__ __forceinline__ float sigx(float x) {
    float t = (float)exp(-(double)x);
    return __fdiv_rn(1.0f, __fadd_rn(1.0f, t));
}
// Fast approximate sigmoid — superset selection only.
__device__ __forceinline__ float siga(float x) {
    return __fdividef(1.0f, 1.0f + __expf(-x));
}

// ================= K1: approx scores (whole chip) =================
__global__ void __launch_bounds__(256)
k_score(const float* __restrict__ cls, const float* __restrict__ ctr)
{
    int b = blockIdx.x >> 4, seg = blockIdx.x & 15;
    const float4* clsB = (const float4*)cls + (size_t)b * NA;
    const float*  ctrB = ctr + (size_t)b * NA;
    for (int i = seg * 256 + threadIdx.x; i < NA; i += 4096) {
        float4 c = clsB[i];
        float m  = fmaxf(fmaxf(c.x, c.y), fmaxf(c.z, c.w));   // sig monotone
        float sm = siga(m);
        float sc = siga(ctrB[i]);
        gscore[b][i] = __fsqrt_rn(sm * sc);
    }
}

// ================= K2a: histogram + threshold + compact =================
extern __shared__ unsigned char k2a_smem[];
__global__ void __launch_bounds__(1024)
k_select()
{
    unsigned* hist  = (unsigned*)k2a_smem;             // 16384
    unsigned* chunk = hist + NBINS;                    // 1024
    __shared__ unsigned s_thr, s_cnt;
    int b = blockIdx.x, tid = threadIdx.x;

    for (int i = tid; i < NBINS; i += 1024) hist[i] = 0;
    if (tid == 0) s_cnt = 0;
    __syncthreads();

    for (int i = tid; i < NA; i += 1024)
        atomicAdd(&hist[__float_as_uint(gscore[b][i]) >> 16], 1u);
    __syncthreads();

    { unsigned s = 0; int base = tid * 16;
#pragma unroll
      for (int q = 0; q < 16; ++q) s += hist[base + q];
      chunk[tid] = s; }
    __syncthreads();
    if (tid == 0) {
        unsigned acc = 0; int T = 0;
        for (int c = 1023; c >= 0; --c) {
            unsigned a2 = acc + chunk[c];
            if (a2 >= KTOP) {
                for (int bin = c * 16 + 15; bin >= c * 16; --bin) {
                    acc += hist[bin];
                    if (acc >= KTOP) { T = bin; break; }
                }
                break;
            }
            acc = a2;
        }
        s_thr = (unsigned)(T > 0 ? T - 1 : 0);   // one-bin superset margin
    }
    __syncthreads();
    const unsigned T = s_thr;

    for (int i = tid; i < NA; i += 1024) {
        if ((__float_as_uint(gscore[b][i]) >> 16) >= T) {
            unsigned p = atomicAdd(&s_cnt, 1u);
            if (p < CCAP) gcidx[b][p] = (unsigned)i;
        }
    }
    __syncthreads();
    if (tid == 0) gcnt[b] = (s_cnt > CCAP) ? CCAP : s_cnt;
}

// ================= K2b: exact rescore (whole chip, FP64) =================
__global__ void __launch_bounds__(256)
k_rescore(const float* __restrict__ cls, const float* __restrict__ ctr)
{
    int b = blockIdx.y;
    unsigned C = gcnt[b];
    const float4* clsB = (const float4*)cls + (size_t)b * NA;
    for (unsigned p = blockIdx.x * 256 + threadIdx.x; p < C; p += 2048) {
        unsigned idx = gcidx[b][p];
        float4 c = clsB[idx];
        float s0 = sigx(c.x), s1 = sigx(c.y), s2 = sigx(c.z), s3 = sigx(c.w);
        float m = s0; unsigned lab = 1;
        if (s1 > m) { m = s1; lab = 2; }
        if (s2 > m) { m = s2; lab = 3; }
        if (s3 > m) { m = s3; lab = 4; }
        float sctr  = sigx(ctr[(size_t)b * NA + idx]);
        float score = __fsqrt_rn(__fmul_rn(m, sctr));
        gkey[b][p] = ((unsigned long long)__float_as_uint(score) << 32)
                   | ((unsigned long long)(0x7FFFu - idx) << 4)
                   | (unsigned long long)lab;
    }
}

// ================= K2c: sort + top-1000 boxes/offsets =================
__global__ void __launch_bounds__(1024)
k_sort(const float* __restrict__ reg, const float* __restrict__ coords,
       const float* __restrict__ pstr)
{
    __shared__ unsigned long long cand[CCAP];
    __shared__ float redmax[32], redmin[32];
    __shared__ float s_mx, s_mn;
    int b = blockIdx.x, tid = threadIdx.x;
    int lane = tid & 31, wid = tid >> 5;

    int C = (int)gcnt[b];
    int S = (C <= 1024) ? 1024 : (C <= 2048 ? 2048 : CCAP);
    for (int i = tid; i < S; i += 1024)
        cand[i] = (i < C) ? gkey[b][i] : 0ULL;
    __syncthreads();

    for (int k2 = 2; k2 <= S; k2 <<= 1)
        for (int j = k2 >> 1; j > 0; j >>= 1) {
            for (int t = tid; t < S; t += 1024) {
                int ixj = t ^ j;
                if (ixj > t) {
                    unsigned long long a = cand[t], b2 = cand[ixj];
                    bool up = ((t & k2) == 0);
                    if (up ? (a < b2) : (a > b2)) { cand[t] = b2; cand[ixj] = a; }
                }
            }
            __syncthreads();
        }

    float x1 = 0, y1 = 0, x2 = 0, y2 = 0, score = 0;
    int label = 0; bool validf = false;
    if (tid < KTOP) {
        unsigned long long key = cand[tid];
        score  = __uint_as_float((unsigned)(key >> 32));
        label  = (int)(key & 0xFull);
        int idx = 0x7FFF - (int)((key >> 4) & 0x7FFFull);
        validf = (score >= 0.05f);

        float4 r4 = ((const float4*)reg)[(size_t)b * NA + idx];
        float2 xy = ((const float2*)coords)[idx];
        float  st = pstr[idx];
        x1 = __fsub_rn(xy.x, __fmul_rn(r4.x, st));
        y1 = __fsub_rn(xy.y, __fmul_rn(r4.y, st));
        x2 = __fadd_rn(xy.x, __fmul_rn(r4.z, st));
        y2 = __fadd_rn(xy.y, __fmul_rn(r4.w, st));
        x1 = fminf(fmaxf(x1, 0.0f), 1023.0f);
        y1 = fminf(fmaxf(y1, 0.0f), 799.0f);
        x2 = fminf(fmaxf(x2, 0.0f), 1023.0f);
        y2 = fminf(fmaxf(y2, 0.0f), 799.0f);

        gsbox[b][tid] = make_float4(x1, y1, x2, y2);
        gssc[b][tid]  = score;
        gslab[b][tid] = (unsigned)label;
        gsval[b][tid] = validf ? 1u : 0u;
    }

    float vmax = -1000000000.0f, vmin = 1000000000.0f;
    if (tid < KTOP && validf) {
        vmax = fmaxf(fmaxf(x1, y1), fmaxf(x2, y2));
        vmin = fminf(fminf(x1, y1), fminf(x2, y2));
    }
#pragma unroll
    for (int o = 16; o; o >>= 1) {
        vmax = fmaxf(vmax, __shfl_xor_sync(0xffffffffu, vmax, o));
        vmin = fminf(vmin, __shfl_xor_sync(0xffffffffu, vmin, o));
    }
    if (lane == 0) { redmax[wid] = vmax; redmin[wid] = vmin; }
    __syncthreads();
    if (tid == 0) {
        float mx = redmax[0], mn = redmin[0];
        for (int w = 1; w < 32; ++w) { mx = fmaxf(mx, redmax[w]); mn = fminf(mn, redmin[w]); }
        s_mx = mx; s_mn = mn;
    }
    __syncthreads();

    if (tid < KTOP) {
        float off = __fmul_rn((float)label, __fadd_rn(__fsub_rn(s_mx, s_mn), 1.0f));
        float a  = __fadd_rn(x1, off), bb = __fadd_rn(y1, off);
        float cc = __fadd_rn(x2, off), dd = __fadd_rn(y2, off);
        gsx1[b][tid] = a;  gsy1[b][tid] = bb;
        gsx2[b][tid] = cc; gsy2[b][tid] = dd;
        gsar[b][tid] = __fmul_rn(__fsub_rn(cc, a), __fsub_rn(dd, bb));
    }
}

// ================= K3: suppression bit-matrix (whole chip) =================
__global__ void __launch_bounds__(1024)
k_matrix()
{
    __shared__ float sx1[KTOP], sy1[KTOP], sx2[KTOP], sy2[KTOP], sar[KTOP];
    int b = blockIdx.y, seg = blockIdx.x;
    int tid = threadIdx.x, lane = tid & 31, wid = tid >> 5;

    for (int j = tid; j < KTOP; j += 1024) {
        sx1[j] = gsx1[b][j]; sy1[j] = gsy1[b][j];
        sx2[j] = gsx2[b][j]; sy2[j] = gsy2[b][j];
        sar[j] = gsar[b][j];
    }
    __syncthreads();

    int i0 = seg * 125, i1 = i0 + 125;
    for (int i = i0 + wid; i < i1; i += 32) {
        float ax1 = sx1[i], ay1 = sy1[i], ax2 = sx2[i], ay2 = sy2[i], aa = sar[i];
        unsigned myword = 0;
        for (int jc = 0; jc < 32; ++jc) {
            int jbase = jc * 32;
            unsigned wbits = 0;
            if (jbase + 31 > i) {
                int j = jbase + lane;
                bool sup = false;
                if (j > i && j < KTOP) {
                    float ix1 = fmaxf(ax1, sx1[j]);
                    float iy1 = fmaxf(ay1, sy1[j]);
                    float ix2 = fminf(ax2, sx2[j]);
                    float iy2 = fminf(ay2, sy2[j]);
                    float iw  = fmaxf(__fsub_rn(ix2, ix1), 0.0f);
                    float ih  = fmaxf(__fsub_rn(iy2, iy1), 0.0f);
                    float inter = __fmul_rn(iw, ih);
                    float uni = fmaxf(__fsub_rn(__fadd_rn(aa, sar[j]), inter), 1e-9f);
                    sup = __fdiv_rn(inter, uni) > 0.5f;
                }
                wbits = __ballot_sync(0xffffffffu, sup);
            }
            if (lane == jc) myword = wbits;
        }
        gmat[b][i][lane] = myword;
    }
}

// ================= K4: serial greedy NMS + outputs =================
extern __shared__ unsigned char k4_smem[];
__global__ void __launch_bounds__(1024)
k_nms(float* __restrict__ out)
{
    unsigned* smat  = (unsigned*)k4_smem;            // 32000 u32
    unsigned* ssval = smat + KTOP * 32;              // 1024
    unsigned* srem  = ssval + 1024;                  // 32
    int b = blockIdx.x, tid = threadIdx.x, lane = tid & 31, wid = tid >> 5;

    { const uint4* src = (const uint4*)&gmat[b][0][0];
      uint4* dst = (uint4*)smat;
      for (int t = tid; t < KTOP * 8; t += 1024) dst[t] = src[t]; }
    for (int t = tid; t < 1024; t += 1024)
        ssval[t] = (t < KTOP) ? gsval[b][t] : 0u;
    __syncthreads();

    if (wid == 0) {
        unsigned removed = 0;                         // lane owns j in [32*lane, 32*lane+32)
#pragma unroll
        for (int jj = 0; jj < 32; ++jj)
            removed |= (ssval[lane * 32 + jj] ? 0u : 1u) << jj;

        int cur = -1;
        while (true) {
            unsigned avail = ~removed;
            int curLane = cur >> 5;
            unsigned m;
            if (lane < curLane)       m = 0u;
            else if (lane == curLane) m = avail & (0xFFFFFFFEu << (cur & 31));
            else                      m = avail;
            unsigned bal = __ballot_sync(0xffffffffu, m != 0u);
            if (!bal) break;
            int src = __ffs(bal) - 1;
            unsigned mm = __shfl_sync(0xffffffffu, m, src);
            int i = src * 32 + __ffs(mm) - 1;         // next kept box
            removed |= smat[i * 32 + lane];           // suppress its overlaps (j>i only)
            cur = i;
        }
        srem[lane] = removed;
    }
    __syncthreads();

    if (tid < KTOP) {
        bool k = ((srem[tid >> 5] >> (tid & 31)) & 1u) == 0u;
        float so = k ? gssc[b][tid] : 0.0f;
        float lo = k ? (float)gslab[b][tid] : 0.0f;
        float4 bx = gsbox[b][tid];
        if (!k) bx = make_float4(0.f, 0.f, 0.f, 0.f);
        out[(size_t)b * KTOP + tid] = so;
        out[(size_t)(B * KTOP) + (size_t)b * KTOP + tid] = lo;
        size_t base = (size_t)(2 * B * KTOP) + ((size_t)b * KTOP + tid) * 4;
        out[base + 0] = bx.x; out[base + 1] = bx.y;
        out[base + 2] = bx.z; out[base + 3] = bx.w;
    }
}

// ================= host =================
extern "C" void kernel_launch(void* const* d_in, const int* in_sizes, int n_in,
                              void* d_out, int out_size) {
    (void)in_sizes; (void)n_in; (void)out_size;
    const float* cls    = (const float*)d_in[0];
    const float* ctr    = (const float*)d_in[1];
    const float* reg    = (const float*)d_in[2];
    const float* coords = (const float*)d_in[3];
    const float* pstr   = (const float*)d_in[4];
    float* out = (float*)d_out;

    static bool attr_done = false;
    if (!attr_done) {
        cudaFuncSetAttribute(k_select, cudaFuncAttributeMaxDynamicSharedMemorySize,
                             (NBINS + 1024) * 4);
        cudaFuncSetAttribute(k_nms, cudaFuncAttributeMaxDynamicSharedMemorySize,
                             (KTOP * 32 + 1024 + 32) * 4);
        attr_done = true;
    }

    k_score  <<<256, 256>>>(cls, ctr);
    k_select <<<16, 1024, (NBINS + 1024) * 4>>>();
    k_rescore<<<dim3(8, 16), 256>>>(cls, ctr);
    k_sort   <<<16, 1024>>>(reg, coords, pstr);
    k_matrix <<<dim3(8, 16), 1024>>>();
    k_nms    <<<16, 1024, (KTOP * 32 + 1024 + 32) * 4>>>(out);
}

// round 4
// speedup vs baseline: 1.8005x; 1.0150x over previous
#include <cuda_runtime.h>
#include <cstdint>

#define NA     17064
#define KTOP   1000
#define NBINS  16384
#define CCAP   4096
#define B      16

typedef unsigned long long u64;

// ---------------- static device scratch ----------------
__device__ float    gscore[B][NA];
__device__ unsigned ghist[B][NBINS];          // zero-init; re-zeroed by k_select
__device__ unsigned gcidx[B][CCAP];
__device__ unsigned gcnt[B];
__device__ u64      gkey[B][CCAP];
__device__ float    gssc[B][KTOP];
__device__ unsigned gslab[B][KTOP];
__device__ unsigned gsval[B][KTOP];
__device__ float4   gsbox[B][KTOP];
__device__ float    gsx1[B][KTOP], gsy1[B][KTOP], gsx2[B][KTOP],
                    gsy2[B][KTOP], gsar[B][KTOP];
__device__ unsigned gmat[B][KTOP][32];

// Exact sigmoid: float exp via double exp (correctly rounded to float =>
// matches faithful libm expf), then float add + div as XLA expands logistic.
__device__ __forceinline__ float sigx(float x) {
    float t = (float)exp(-(double)x);
    return __fdiv_rn(1.0f, __fadd_rn(1.0f, t));
}
// Fast approximate sigmoid — superset selection only.
__device__ __forceinline__ float siga(float x) {
    return __fdividef(1.0f, 1.0f + __expf(-x));
}

// ================= K1: approx scores + global histogram =================
__global__ void __launch_bounds__(256)
k_score(const float* __restrict__ cls, const float* __restrict__ ctr)
{
    int b = blockIdx.x >> 4, seg = blockIdx.x & 15;
    const float4* clsB = (const float4*)cls + (size_t)b * NA;
    const float*  ctrB = ctr + (size_t)b * NA;
    for (int i = seg * 256 + threadIdx.x; i < NA; i += 4096) {
        float4 c = clsB[i];
        float m  = fmaxf(fmaxf(c.x, c.y), fmaxf(c.z, c.w));   // sig monotone
        float score = __fsqrt_rn(siga(m) * siga(ctrB[i]));
        gscore[b][i] = score;
        atomicAdd(&ghist[b][__float_as_uint(score) >> 16], 1u);
    }
}

// ================= K2a: threshold + compact (re-zeros ghist) =================
__global__ void __launch_bounds__(1024)
k_select()
{
    __shared__ unsigned chunk[1024];
    __shared__ unsigned s_thr, s_cnt;
    int b = blockIdx.x, tid = threadIdx.x;
    if (tid == 0) s_cnt = 0;

    { unsigned s = 0; int base = tid * 16;
#pragma unroll
      for (int q = 0; q < 16; ++q) s += ghist[b][base + q];
      chunk[tid] = s; }
    __syncthreads();
    if (tid == 0) {
        unsigned acc = 0; int T = 0;
        for (int c = 1023; c >= 0; --c) {
            unsigned a2 = acc + chunk[c];
            if (a2 >= KTOP) {
                for (int bin = c * 16 + 15; bin >= c * 16; --bin) {
                    acc += ghist[b][bin];
                    if (acc >= KTOP) { T = bin; break; }
                }
                break;
            }
            acc = a2;
        }
        s_thr = (unsigned)(T > 0 ? T - 1 : 0);   // one-bin superset margin
    }
    __syncthreads();
    const unsigned T = s_thr;

    for (int i = tid; i < NA; i += 1024) {
        if ((__float_as_uint(gscore[b][i]) >> 16) >= T) {
            unsigned p = atomicAdd(&s_cnt, 1u);
            if (p < CCAP) gcidx[b][p] = (unsigned)i;
        }
    }
    // re-zero histogram for next graph replay (atomics accumulate)
    for (int i = tid; i < NBINS; i += 1024) ghist[b][i] = 0;
    __syncthreads();
    if (tid == 0) gcnt[b] = (s_cnt > CCAP) ? CCAP : s_cnt;
}

// ================= K2b: exact rescore — 2 FP64 exps per candidate =========
__global__ void __launch_bounds__(256)
k_rescore(const float* __restrict__ cls, const float* __restrict__ ctr)
{
    int b = blockIdx.y;
    unsigned C = gcnt[b];
    const float4* clsB = (const float4*)cls + (size_t)b * NA;
    for (unsigned p = blockIdx.x * 256 + threadIdx.x; p < C; p += 2048) {
        unsigned idx = gcidx[b][p];
        float4 c = clsB[idx];
        float xs0 = c.x, xs1 = c.y, xs2 = c.z, xs3 = c.w;
        float m = xs0; int im = 0;
        if (xs1 > m) { m = xs1; im = 1; }
        if (xs2 > m) { m = xs2; im = 2; }
        if (xs3 > m) { m = xs3; im = 3; }
        float sm = sigx(m);                       // == max of the 4 sigmoids
        int lab = im;
        // tie guard: earlier smaller logit whose sigmoid rounds equal
        if (im > 0) {
            float lim = m - 1e-4f;
            if ((im > 0 && xs0 > lim) || (im > 1 && xs1 > lim) || (im > 2 && xs2 > lim)) {
                if (im > 0 && xs0 > lim && sigx(xs0) == sm) lab = 0;
                else if (im > 1 && xs1 > lim && sigx(xs1) == sm) lab = 1;
                else if (im > 2 && xs2 > lim && sigx(xs2) == sm) lab = 2;
            }
        }
        float sctr  = sigx(ctr[(size_t)b * NA + idx]);
        float score = __fsqrt_rn(__fmul_rn(sm, sctr));
        gkey[b][p] = ((u64)__float_as_uint(score) << 32)
                   | ((u64)(0x7FFFu - idx) << 4)
                   | (u64)(lab + 1);
    }
}

// ---- compare-exchange helpers (descending network) ----
__device__ __forceinline__ u64 cex_shfl(u64 v, int j, bool up, int lane) {
    u64 p = __shfl_xor_sync(0xffffffffu, v, j);
    bool lower = ((lane & j) == 0);
    return (lower == up) ? (v > p ? v : p) : (v < p ? v : p);
}

// ================= K2c: hybrid bitonic sort + top-1000 boxes =================
__global__ void __launch_bounds__(1024)
k_sort(const float* __restrict__ reg, const float* __restrict__ coords,
       const float* __restrict__ pstr)
{
    __shared__ u64 cand[CCAP];
    __shared__ float redmax[32], redmin[32];
    __shared__ float s_mx, s_mn;
    int b = blockIdx.x, tid = threadIdx.x;
    int lane = tid & 31, wid = tid >> 5;

    int C = (int)gcnt[b];

    if (C <= 2048) {
        // ---- hybrid register/smem bitonic over 2048 elements ----
        const int base = wid * 64;
        u64 r0 = (base + lane      < C) ? gkey[b][base + lane]      : 0ULL;
        u64 r1 = (base + 32 + lane < C) ? gkey[b][base + 32 + lane] : 0ULL;

        // stages k2 = 2..16: per-lane direction, both regs identical rule
#pragma unroll
        for (int k2 = 2; k2 <= 16; k2 <<= 1) {
            bool up = ((lane & k2) == 0);
#pragma unroll
            for (int j = k2 >> 1; j > 0; j >>= 1) {
                r0 = cex_shfl(r0, j, up, lane);
                r1 = cex_shfl(r1, j, up, lane);
            }
        }
        // stage k2 = 32: r0 up, r1 down
#pragma unroll
        for (int j = 16; j > 0; j >>= 1) {
            r0 = cex_shfl(r0, j, true,  lane);
            r1 = cex_shfl(r1, j, false, lane);
        }
        // stage k2 = 64: pair step + shfl steps, warp-uniform direction
        {
            bool up = ((base & 64) == 0);
            u64 lo = r0, hi = r1;
            if (up) { r0 = lo > hi ? lo : hi; r1 = lo > hi ? hi : lo; }
            else    { r0 = lo < hi ? lo : hi; r1 = lo < hi ? hi : lo; }
#pragma unroll
            for (int j = 16; j > 0; j >>= 1) {
                r0 = cex_shfl(r0, j, up, lane);
                r1 = cex_shfl(r1, j, up, lane);
            }
        }
        // stages k2 = 128..2048: smem for j>=64, regs for j<=32
        for (int k2 = 128; k2 <= 2048; k2 <<= 1) {
            cand[base + lane] = r0; cand[base + 32 + lane] = r1;
            __syncthreads();
            for (int j = k2 >> 1; j >= 64; j >>= 1) {
                for (int t = tid; t < 2048; t += 1024) {
                    int ixj = t ^ j;
                    if (ixj > t) {
                        u64 a = cand[t], b2 = cand[ixj];
                        bool up = ((t & k2) == 0);
                        if (up ? (a < b2) : (a > b2)) { cand[t] = b2; cand[ixj] = a; }
                    }
                }
                __syncthreads();
            }
            r0 = cand[base + lane]; r1 = cand[base + 32 + lane];
            bool up = ((base & k2) == 0);
            u64 lo = r0, hi = r1;
            if (up) { r0 = lo > hi ? lo : hi; r1 = lo > hi ? hi : lo; }
            else    { r0 = lo < hi ? lo : hi; r1 = lo < hi ? hi : lo; }
#pragma unroll
            for (int j = 16; j > 0; j >>= 1) {
                r0 = cex_shfl(r0, j, up, lane);
                r1 = cex_shfl(r1, j, up, lane);
            }
        }
        cand[base + lane] = r0; cand[base + 32 + lane] = r1;
        __syncthreads();
    } else {
        // ---- fallback: plain smem bitonic over 4096 ----
        for (int i = tid; i < CCAP; i += 1024)
            cand[i] = (i < C) ? gkey[b][i] : 0ULL;
        __syncthreads();
        for (int k2 = 2; k2 <= CCAP; k2 <<= 1)
            for (int j = k2 >> 1; j > 0; j >>= 1) {
                for (int t = tid; t < CCAP; t += 1024) {
                    int ixj = t ^ j;
                    if (ixj > t) {
                        u64 a = cand[t], b2 = cand[ixj];
                        bool up = ((t & k2) == 0);
                        if (up ? (a < b2) : (a > b2)) { cand[t] = b2; cand[ixj] = a; }
                    }
                }
                __syncthreads();
            }
    }

    // ---- gather top-1000, build boxes ----
    float x1 = 0, y1 = 0, x2 = 0, y2 = 0, score = 0;
    int label = 0; bool validf = false;
    if (tid < KTOP) {
        u64 key = cand[tid];
        score  = __uint_as_float((unsigned)(key >> 32));
        label  = (int)(key & 0xFull);
        int idx = 0x7FFF - (int)((key >> 4) & 0x7FFFull);
        validf = (score >= 0.05f);

        float4 r4 = ((const float4*)reg)[(size_t)b * NA + idx];
        float2 xy = ((const float2*)coords)[idx];
        float  st = pstr[idx];
        x1 = __fsub_rn(xy.x, __fmul_rn(r4.x, st));
        y1 = __fsub_rn(xy.y, __fmul_rn(r4.y, st));
        x2 = __fadd_rn(xy.x, __fmul_rn(r4.z, st));
        y2 = __fadd_rn(xy.y, __fmul_rn(r4.w, st));
        x1 = fminf(fmaxf(x1, 0.0f), 1023.0f);
        y1 = fminf(fmaxf(y1, 0.0f), 799.0f);
        x2 = fminf(fmaxf(x2, 0.0f), 1023.0f);
        y2 = fminf(fmaxf(y2, 0.0f), 799.0f);

        gsbox[b][tid] = make_float4(x1, y1, x2, y2);
        gssc[b][tid]  = score;
        gslab[b][tid] = (unsigned)label;
        gsval[b][tid] = validf ? 1u : 0u;
    }

    float vmax = -1000000000.0f, vmin = 1000000000.0f;
    if (tid < KTOP && validf) {
        vmax = fmaxf(fmaxf(x1, y1), fmaxf(x2, y2));
        vmin = fminf(fminf(x1, y1), fminf(x2, y2));
    }
#pragma unroll
    for (int o = 16; o; o >>= 1) {
        vmax = fmaxf(vmax, __shfl_xor_sync(0xffffffffu, vmax, o));
        vmin = fminf(vmin, __shfl_xor_sync(0xffffffffu, vmin, o));
    }
    if (lane == 0) { redmax[wid] = vmax; redmin[wid] = vmin; }
    __syncthreads();
    if (tid == 0) {
        float mx = redmax[0], mn = redmin[0];
        for (int w = 1; w < 32; ++w) { mx = fmaxf(mx, redmax[w]); mn = fminf(mn, redmin[w]); }
        s_mx = mx; s_mn = mn;
    }
    __syncthreads();

    if (tid < KTOP) {
        float off = __fmul_rn((float)label, __fadd_rn(__fsub_rn(s_mx, s_mn), 1.0f));
        float a  = __fadd_rn(x1, off), bb = __fadd_rn(y1, off);
        float cc = __fadd_rn(x2, off), dd = __fadd_rn(y2, off);
        gsx1[b][tid] = a;  gsy1[b][tid] = bb;
        gsx2[b][tid] = cc; gsy2[b][tid] = dd;
        gsar[b][tid] = __fmul_rn(__fsub_rn(cc, a), __fsub_rn(dd, bb));
    }
}

// ================= K3: suppression bit-matrix (whole chip) =================
__global__ void __launch_bounds__(1024)
k_matrix()
{
    __shared__ float sx1[KTOP], sy1[KTOP], sx2[KTOP], sy2[KTOP], sar[KTOP];
    int b = blockIdx.y, seg = blockIdx.x;
    int tid = threadIdx.x, lane = tid & 31, wid = tid >> 5;

    for (int j = tid; j < KTOP; j += 1024) {
        sx1[j] = gsx1[b][j]; sy1[j] = gsy1[b][j];
        sx2[j] = gsx2[b][j]; sy2[j] = gsy2[b][j];
        sar[j] = gsar[b][j];
    }
    __syncthreads();

    int i0 = seg * 125, i1 = i0 + 125;
    for (int i = i0 + wid; i < i1; i += 32) {
        float ax1 = sx1[i], ay1 = sy1[i], ax2 = sx2[i], ay2 = sy2[i], aa = sar[i];
        unsigned myword = 0;
        for (int jc = 0; jc < 32; ++jc) {
            int jbase = jc * 32;
            unsigned wbits = 0;
            if (jbase + 31 > i) {
                int j = jbase + lane;
                bool sup = false;
                if (j > i && j < KTOP) {
                    float ix1 = fmaxf(ax1, sx1[j]);
                    float iy1 = fmaxf(ay1, sy1[j]);
                    float ix2 = fminf(ax2, sx2[j]);
                    float iy2 = fminf(ay2, sy2[j]);
                    float iw  = fmaxf(__fsub_rn(ix2, ix1), 0.0f);
                    float ih  = fmaxf(__fsub_rn(iy2, iy1), 0.0f);
                    float inter = __fmul_rn(iw, ih);
                    float uni = fmaxf(__fsub_rn(__fadd_rn(aa, sar[j]), inter), 1e-9f);
                    sup = __fdiv_rn(inter, uni) > 0.5f;
                }
                wbits = __ballot_sync(0xffffffffu, sup);
            }
            if (lane == jc) myword = wbits;
        }
        gmat[b][i][lane] = myword;
    }
}

// ================= K4: serial greedy NMS + outputs =================
extern __shared__ unsigned char k4_smem[];
__global__ void __launch_bounds__(1024)
k_nms(float* __restrict__ out)
{
    unsigned* smat  = (unsigned*)k4_smem;            // 32000 u32
    unsigned* ssval = smat + KTOP * 32;              // 1024
    unsigned* srem  = ssval + 1024;                  // 32
    int b = blockIdx.x, tid = threadIdx.x, lane = tid & 31, wid = tid >> 5;

    { const uint4* src = (const uint4*)&gmat[b][0][0];
      uint4* dst = (uint4*)smat;
      for (int t = tid; t < KTOP * 8; t += 1024) dst[t] = src[t]; }
    ssval[tid] = (tid < KTOP) ? gsval[b][tid] : 0u;
    __syncthreads();

    if (wid == 0) {
        unsigned removed = 0;                         // lane owns [32*lane, 32*lane+32)
#pragma unroll
        for (int jj = 0; jj < 32; ++jj)
            removed |= (ssval[lane * 32 + jj] ? 0u : 1u) << jj;

        int cur = -1;
        while (true) {
            unsigned avail = ~removed;
            int curLane = cur >> 5;
            unsigned m;
            if (lane < curLane)       m = 0u;
            else if (lane == curLane) m = avail & (0xFFFFFFFEu << (cur & 31));
            else                      m = avail;
            unsigned bal = __ballot_sync(0xffffffffu, m != 0u);
            if (!bal) break;
            int src = __ffs(bal) - 1;
            unsigned mm = __shfl_sync(0xffffffffu, m, src);
            int i = src * 32 + __ffs(mm) - 1;         // next kept box
            removed |= smat[i * 32 + lane];
            cur = i;
        }
        srem[lane] = removed;
    }
    __syncthreads();

    if (tid < KTOP) {
        bool k = ((srem[tid >> 5] >> (tid & 31)) & 1u) == 0u;
        float so = k ? gssc[b][tid] : 0.0f;
        float lo = k ? (float)gslab[b][tid] : 0.0f;
        float4 bx = gsbox[b][tid];
        if (!k) bx = make_float4(0.f, 0.f, 0.f, 0.f);
        out[(size_t)b * KTOP + tid] = so;
        out[(size_t)(B * KTOP) + (size_t)b * KTOP + tid] = lo;
        size_t base = (size_t)(2 * B * KTOP) + ((size_t)b * KTOP + tid) * 4;
        out[base + 0] = bx.x; out[base + 1] = bx.y;
        out[base + 2] = bx.z; out[base + 3] = bx.w;
    }
}

// ================= host =================
extern "C" void kernel_launch(void* const* d_in, const int* in_sizes, int n_in,
                              void* d_out, int out_size) {
    (void)in_sizes; (void)n_in; (void)out_size;
    const float* cls    = (const float*)d_in[0];
    const float* ctr    = (const float*)d_in[1];
    const float* reg    = (const float*)d_in[2];
    const float* coords = (const float*)d_in[3];
    const float* pstr   = (const float*)d_in[4];
    float* out = (float*)d_out;

    static bool attr_done = false;
    if (!attr_done) {
        cudaFuncSetAttribute(k_nms, cudaFuncAttributeMaxDynamicSharedMemorySize,
                             (KTOP * 32 + 1024 + 32) * 4);
        attr_done = true;
    }

    k_score  <<<256, 256>>>(cls, ctr);
    k_select <<<16, 1024>>>();
    k_rescore<<<dim3(8, 16), 256>>>(cls, ctr);
    k_sort   <<<16, 1024>>>(reg, coords, pstr);
    k_matrix <<<dim3(8, 16), 1024>>>();
    k_nms    <<<16, 1024, (KTOP * 32 + 1024 + 32) * 4>>>(out);
}